// round 9
// baseline (speedup 1.0000x reference)
#include <cuda_runtime.h>
#include <cuda_fp16.h>
#include <cstdint>

// ---------------- problem constants ----------------
#define MROWS 8192          // B*S = 4*2048
#define KDIM  2048
#define NCOLS 6144          // 3*D fused QKV
#define LN_EPS 1e-5f

// ---------------- GEMM tiling ----------------
#define BM 128
#define BN 128
#define BK 64
#define NKT (KDIM / BK)     // 32 k-chunks
#define NSTAGE 3

#define A_TILE_BYTES 16384          // 128 rows x 128B
#define B_TILE_BYTES 16384          // 128 rows x 128B
#define STAGE_BYTES  (A_TILE_BYTES + B_TILE_BYTES)   // 32768
#define GEMM_SMEM    (NSTAGE * STAGE_BYTES)          // 98304 -> 2 CTAs/SM

// ---------------- scratch (static device memory: allowed) ----------------
__device__ __half g_A[(size_t)MROWS * KDIM];   // 32 MB
__device__ __half g_W[(size_t)NCOLS * KDIM];   // 24 MB
__device__ float  g_bias[NCOLS];

// ---------------- helpers ----------------
__device__ __forceinline__ uint32_t smem_u32(const void* p) {
    return (uint32_t)__cvta_generic_to_shared(p);
}
__device__ __forceinline__ uint32_t swz128(uint32_t b) {
    return b ^ ((b >> 3) & 0x70);
}
__device__ __forceinline__ void cp16(uint32_t dst, const void* src) {
    asm volatile("cp.async.cg.shared.global [%0], [%1], 16;\n"
                 :: "r"(dst), "l"(src) : "memory");
}
__device__ __forceinline__ void cp_commit() {
    asm volatile("cp.async.commit_group;" ::: "memory");
}
__device__ __forceinline__ void ldsm_x4(uint32_t addr, uint32_t r[4]) {
    asm volatile("ldmatrix.sync.aligned.m8n8.x4.shared.b16 {%0,%1,%2,%3}, [%4];"
                 : "=r"(r[0]), "=r"(r[1]), "=r"(r[2]), "=r"(r[3]) : "r"(addr));
}
__device__ __forceinline__ void mma_f16(float c[4], const uint32_t a[4],
                                        const uint32_t b0, const uint32_t b1) {
    asm volatile(
        "mma.sync.aligned.m16n8k16.row.col.f32.f16.f16.f32 "
        "{%0,%1,%2,%3}, {%4,%5,%6,%7}, {%8,%9}, {%0,%1,%2,%3};"
        : "+f"(c[0]), "+f"(c[1]), "+f"(c[2]), "+f"(c[3])
        : "r"(a[0]), "r"(a[1]), "r"(a[2]), "r"(a[3]), "r"(b0), "r"(b1));
}
__device__ __forceinline__ uint2 pack4h(float a, float b, float c, float d) {
    __half2 p0 = __halves2half2(__float2half_rn(a), __float2half_rn(b));
    __half2 p1 = __halves2half2(__float2half_rn(c), __float2half_rn(d));
    uint2 u;
    u.x = *reinterpret_cast<uint32_t*>(&p0);
    u.y = *reinterpret_cast<uint32_t*>(&p1);
    return u;
}

// ====================================================================
// Kernel 1: fused prep.
//   blocks [0, MROWS):              LayerNorm row -> fp16 g_A
//   blocks [MROWS, MROWS+NCOLS):    weight row fp32->fp16 g_W + bias
// ====================================================================
__global__ __launch_bounds__(256) void prep_kernel(
    const float* __restrict__ x, const float* __restrict__ nw,
    const float* __restrict__ nb,
    const float* __restrict__ qw, const float* __restrict__ kw,
    const float* __restrict__ vw, const float* __restrict__ qb,
    const float* __restrict__ kb, const float* __restrict__ vb)
{
    const int tid = threadIdx.x;

    if (blockIdx.x >= MROWS) {
        // ---- weight convert path ----
        const int n = blockIdx.x - MROWS;
        const float* src;
        if (n < 2048) {
            src = qw + (size_t)n * KDIM;
            if (tid == 0) g_bias[n] = qb[n];
        } else if (n < 4096) {
            src = kw + (size_t)(n - 2048) * KDIM;
            if (tid == 0) g_bias[n] = kb[n - 2048];
        } else {
            src = vw + (size_t)(n - 4096) * KDIM;
            if (tid == 0) g_bias[n] = vb[n - 4096];
        }
        const float4* sr = reinterpret_cast<const float4*>(src);
        uint2* rowp = reinterpret_cast<uint2*>(g_W + (size_t)n * KDIM);
        #pragma unroll
        for (int jj = 0; jj < 2; jj++) {
            const int j = tid + 256 * jj;
            const float4 v = sr[j];
            rowp[j] = pack4h(v.x, v.y, v.z, v.w);
        }
        return;
    }

    // ---- LayerNorm path ----
    const int row = blockIdx.x;
    const float4* xr = reinterpret_cast<const float4*>(x + (size_t)row * KDIM);

    float4 v0 = xr[tid];
    float4 v1 = xr[tid + 256];

    float s = v0.x + v0.y + v0.z + v0.w + v1.x + v1.y + v1.z + v1.w;
    float q = v0.x*v0.x + v0.y*v0.y + v0.z*v0.z + v0.w*v0.w +
              v1.x*v1.x + v1.y*v1.y + v1.z*v1.z + v1.w*v1.w;

    #pragma unroll
    for (int o = 16; o > 0; o >>= 1) {
        s += __shfl_xor_sync(0xffffffffu, s, o);
        q += __shfl_xor_sync(0xffffffffu, q, o);
    }

    __shared__ float red[2][8];
    __shared__ float mu_s, rs_s;
    const int wid = tid >> 5, lane = tid & 31;
    if (lane == 0) { red[0][wid] = s; red[1][wid] = q; }
    __syncthreads();
    if (tid == 0) {
        float ss = 0.f, qq = 0.f;
        #pragma unroll
        for (int i = 0; i < 8; i++) { ss += red[0][i]; qq += red[1][i]; }
        float mu  = ss * (1.0f / KDIM);
        float var = qq * (1.0f / KDIM) - mu * mu;
        mu_s = mu;
        rs_s = rsqrtf(var + LN_EPS);
    }
    __syncthreads();
    const float mu = mu_s, rs = rs_s;

    const float4* wr = reinterpret_cast<const float4*>(nw);
    const float4* br = reinterpret_cast<const float4*>(nb);
    uint2* rowp = reinterpret_cast<uint2*>(g_A + (size_t)row * KDIM);

    #pragma unroll
    for (int jj = 0; jj < 2; jj++) {
        const int j = tid + 256 * jj;          // float4-chunk index 0..511
        const float4 xv = jj ? v1 : v0;
        const float4 wv = wr[j];
        const float4 bv = br[j];
        float o0 = (xv.x - mu) * rs * wv.x + bv.x;
        float o1 = (xv.y - mu) * rs * wv.y + bv.y;
        float o2 = (xv.z - mu) * rs * wv.z + bv.z;
        float o3 = (xv.w - mu) * rs * wv.w + bv.w;
        rowp[j] = pack4h(o0, o1, o2, o3);
    }
}

// ====================================================================
// Kernel 2: fp16 mma.sync GEMM, C[8192x6144] = A[8192x2048] * W[6144x2048]^T
//   256 threads: 8 warps = 2 (M) x 4 (N); warp tile 64x32; BK=64,
//   3 stages, 2 CTAs/SM.  cp.async prefetch is interleaved INTO the
//   compute phase (A-quad under ks=0 MMAs, B-quad under ks=1 MMAs) so
//   the LDGSTS burst no longer queues ahead of the first ldmatrix.
// ====================================================================
__global__ __launch_bounds__(256, 2)
void qkv_gemm_kernel(float* __restrict__ out)
{
    extern __shared__ char smem[];
    const int tid  = threadIdx.x;
    const int wid  = tid >> 5;
    const int lane = tid & 31;
    const int wm   = wid & 1;       // 0..1  (64 rows each)
    const int wn   = wid >> 1;      // 0..3  (32 cols each)
    const uint32_t sbase = smem_u32(smem);

    // tile mapping with group-of-8 m-tile swizzle for L2 reuse
    const int NT = NCOLS / BN;              // 48
    const int GM = 8;
    const int bid = blockIdx.x;
    const int grp = bid / (GM * NT);
    const int rem = bid % (GM * NT);
    const int mt_ = grp * GM + (rem % GM);
    const int nt_ = rem / GM;
    const int m0 = mt_ * BM;
    const int n0 = nt_ * BN;

    const __half* Ag = g_A + (size_t)m0 * KDIM;
    const __half* Wg = g_W + (size_t)n0 * KDIM;

    // per-thread cp.async source/dest pieces (4 chunks each for A and B)
    const int cr = tid >> 3;                 // row   0..31 (base)
    const int cc = tid & 7;                  // 16B col 0..7
    const uint32_t coff[4] = {
        swz128((uint32_t)((cr +  0) * 128 + cc * 16)),
        swz128((uint32_t)((cr + 32) * 128 + cc * 16)),
        swz128((uint32_t)((cr + 64) * 128 + cc * 16)),
        swz128((uint32_t)((cr + 96) * 128 + cc * 16)),
    };

    auto load_stage_all = [&](int s, int kc) {   // used only in prologue
        const uint32_t st = sbase + s * STAGE_BYTES;
        const int k0 = kc * BK;
        #pragma unroll
        for (int j = 0; j < 4; j++)
            cp16(st + coff[j], Ag + (size_t)(cr + 32 * j) * KDIM + k0 + cc * 8);
        #pragma unroll
        for (int j = 0; j < 4; j++)
            cp16(st + A_TILE_BYTES + coff[j],
                 Wg + (size_t)(cr + 32 * j) * KDIM + k0 + cc * 8);
        cp_commit();
    };

    float acc[4][4][4];
    #pragma unroll
    for (int i = 0; i < 4; i++)
        #pragma unroll
        for (int j = 0; j < 4; j++)
            #pragma unroll
            for (int c = 0; c < 4; c++) acc[i][j][c] = 0.f;

    // prologue: 2 chunks in flight
    load_stage_all(0, 0);
    load_stage_all(1, 1);

    // precomputed lane pieces for ldmatrix addressing
    const int a_row_lane = lane & 15;                        // row within m16
    const int a_k_lane   = (lane >> 4) * 8;                  // k half
    const int b_row_lane = (lane & 7) + ((lane >> 4) << 3);  // row within n16
    const int b_k_lane   = ((lane >> 3) & 1) * 8;            // k half

    #pragma unroll 1
    for (int kt = 0; kt < NKT; kt++) {
        const int s = kt % NSTAGE;
        // groups issued so far = kt + 2 (empty commits keep this invariant at
        // the tail); waiting for <=1 pending implies chunk kt is complete.
        asm volatile("cp.async.wait_group 1;" ::: "memory");
        __syncthreads();

        const uint32_t aBase = sbase + s * STAGE_BYTES;
        const uint32_t bBase = aBase + A_TILE_BYTES;

        const bool do_load = (kt + 2 < NKT);
        const uint32_t pst  = sbase + ((kt + 2) % NSTAGE) * STAGE_BYTES;
        const int      pk0  = (kt + 2) * BK;

        #pragma unroll
        for (int ks = 0; ks < 4; ks++) {
            const int k0 = ks * 16;
            uint32_t af[4][4];
            #pragma unroll
            for (int mt = 0; mt < 4; mt++) {
                const int row = wm * 64 + mt * 16 + a_row_lane;
                const uint32_t addr =
                    aBase + swz128((uint32_t)(row * 128 + (k0 + a_k_lane) * 2));
                ldsm_x4(addr, af[mt]);
            }
            uint32_t bf[4][2];
            #pragma unroll
            for (int p = 0; p < 2; p++) {
                const int rown = wn * 32 + p * 16 + b_row_lane;
                const uint32_t addr =
                    bBase + swz128((uint32_t)(rown * 128 + (k0 + b_k_lane) * 2));
                uint32_t r[4];
                ldsm_x4(addr, r);
                bf[2*p][0] = r[0]; bf[2*p][1] = r[1];
                bf[2*p+1][0] = r[2]; bf[2*p+1][1] = r[3];
            }

            // interleaved prefetch: A-quad during ks=0, B-quad+commit at ks=1
            if (ks == 0) {
                if (do_load) {
                    #pragma unroll
                    for (int j = 0; j < 4; j++)
                        cp16(pst + coff[j],
                             Ag + (size_t)(cr + 32 * j) * KDIM + pk0 + cc * 8);
                }
            } else if (ks == 1) {
                if (do_load) {
                    #pragma unroll
                    for (int j = 0; j < 4; j++)
                        cp16(pst + A_TILE_BYTES + coff[j],
                             Wg + (size_t)(cr + 32 * j) * KDIM + pk0 + cc * 8);
                }
                cp_commit();   // real or empty: keeps group count aligned
            }

            #pragma unroll
            for (int mt = 0; mt < 4; mt++)
                #pragma unroll
                for (int nt = 0; nt < 4; nt++)
                    mma_f16(acc[mt][nt], af[mt], bf[nt][0], bf[nt][1]);
        }
    }

    // epilogue: bias + direct stores (32B-sector aligned float2 per quad)
    const int gid = lane >> 2;       // 0..7 row within m8
    const int tq  = lane & 3;        // col pair
    float bb[4][2];
    #pragma unroll
    for (int nt = 0; nt < 4; nt++) {
        const int col = n0 + wn * 32 + nt * 8 + tq * 2;
        bb[nt][0] = g_bias[col];
        bb[nt][1] = g_bias[col + 1];
    }
    #pragma unroll
    for (int mt = 0; mt < 4; mt++) {
        const int row = m0 + wm * 64 + mt * 16 + gid;
        #pragma unroll
        for (int nt = 0; nt < 4; nt++) {
            const int col = n0 + wn * 32 + nt * 8 + tq * 2;
            float2 v0, v1;
            v0.x = acc[mt][nt][0] + bb[nt][0];
            v0.y = acc[mt][nt][1] + bb[nt][1];
            v1.x = acc[mt][nt][2] + bb[nt][0];
            v1.y = acc[mt][nt][3] + bb[nt][1];
            *reinterpret_cast<float2*>(out + (size_t)row * NCOLS + col) = v0;
            *reinterpret_cast<float2*>(out + (size_t)(row + 8) * NCOLS + col) = v1;
        }
    }
}

// ====================================================================
// launch
// ====================================================================
extern "C" void kernel_launch(void* const* d_in, const int* in_sizes, int n_in,
                              void* d_out, int out_size)
{
    const float* x  = (const float*)d_in[0];
    const float* nw = (const float*)d_in[1];
    const float* nb = (const float*)d_in[2];
    const float* qw = (const float*)d_in[3];
    const float* qb = (const float*)d_in[4];
    const float* kw = (const float*)d_in[5];
    const float* kb = (const float*)d_in[6];
    const float* vw = (const float*)d_in[7];
    const float* vb = (const float*)d_in[8];
    float* out = (float*)d_out;

    cudaFuncSetAttribute(qkv_gemm_kernel,
                         cudaFuncAttributeMaxDynamicSharedMemorySize, GEMM_SMEM);

    prep_kernel<<<MROWS + NCOLS, 256>>>(x, nw, nb, qw, kw, vw, qb, kb, vb);
    qkv_gemm_kernel<<<(MROWS / BM) * (NCOLS / BN), 256, GEMM_SMEM>>>(out);
}

// round 10
// speedup vs baseline: 1.1563x; 1.1563x over previous
#include <cuda_runtime.h>
#include <cuda_fp16.h>
#include <cstdint>

// ---------------- problem constants ----------------
#define MROWS 8192          // B*S = 4*2048
#define KDIM  2048
#define NCOLS 6144          // 3*D fused QKV
#define LN_EPS 1e-5f

// ---------------- GEMM tiling ----------------
#define BM 128
#define BN 128
#define BK 64
#define NKT (KDIM / BK)     // 32 k-chunks
#define NSTAGE 3

#define A_TILE_BYTES 16384          // 128 rows x 128B
#define B_TILE_BYTES 16384          // 128 rows x 128B
#define STAGE_BYTES  (A_TILE_BYTES + B_TILE_BYTES)   // 32768
#define GEMM_SMEM    (NSTAGE * STAGE_BYTES)          // 98304 -> 2 CTAs/SM

// ---------------- scratch (static device memory: allowed) ----------------
__device__ __half g_A[(size_t)MROWS * KDIM];   // 32 MB
__device__ __half g_W[(size_t)NCOLS * KDIM];   // 24 MB
__device__ float  g_bias[NCOLS];

// ---------------- helpers ----------------
__device__ __forceinline__ uint32_t smem_u32(const void* p) {
    return (uint32_t)__cvta_generic_to_shared(p);
}
__device__ __forceinline__ uint32_t swz128(uint32_t b) {
    return b ^ ((b >> 3) & 0x70);
}
__device__ __forceinline__ void cp16(uint32_t dst, const void* src) {
    asm volatile("cp.async.cg.shared.global [%0], [%1], 16;\n"
                 :: "r"(dst), "l"(src) : "memory");
}
__device__ __forceinline__ void cp_commit() {
    asm volatile("cp.async.commit_group;" ::: "memory");
}
__device__ __forceinline__ void ldsm_x4(uint32_t addr, uint32_t r[4]) {
    asm volatile("ldmatrix.sync.aligned.m8n8.x4.shared.b16 {%0,%1,%2,%3}, [%4];"
                 : "=r"(r[0]), "=r"(r[1]), "=r"(r[2]), "=r"(r[3]) : "r"(addr));
}
__device__ __forceinline__ void mma_f16(float c[4], const uint32_t a[4],
                                        const uint32_t b0, const uint32_t b1) {
    asm volatile(
        "mma.sync.aligned.m16n8k16.row.col.f32.f16.f16.f32 "
        "{%0,%1,%2,%3}, {%4,%5,%6,%7}, {%8,%9}, {%0,%1,%2,%3};"
        : "+f"(c[0]), "+f"(c[1]), "+f"(c[2]), "+f"(c[3])
        : "r"(a[0]), "r"(a[1]), "r"(a[2]), "r"(a[3]), "r"(b0), "r"(b1));
}
__device__ __forceinline__ uint2 pack4h(float a, float b, float c, float d) {
    __half2 p0 = __halves2half2(__float2half_rn(a), __float2half_rn(b));
    __half2 p1 = __halves2half2(__float2half_rn(c), __float2half_rn(d));
    uint2 u;
    u.x = *reinterpret_cast<uint32_t*>(&p0);
    u.y = *reinterpret_cast<uint32_t*>(&p1);
    return u;
}

// ====================================================================
// Kernel 1: fused prep.
//   blocks [0, MROWS):              LayerNorm row -> fp16 g_A
//   blocks [MROWS, MROWS+NCOLS):    weight row fp32->fp16 g_W + bias
// ====================================================================
__global__ __launch_bounds__(256) void prep_kernel(
    const float* __restrict__ x, const float* __restrict__ nw,
    const float* __restrict__ nb,
    const float* __restrict__ qw, const float* __restrict__ kw,
    const float* __restrict__ vw, const float* __restrict__ qb,
    const float* __restrict__ kb, const float* __restrict__ vb)
{
    const int tid = threadIdx.x;

    if (blockIdx.x >= MROWS) {
        // ---- weight convert path ----
        const int n = blockIdx.x - MROWS;
        const float* src;
        if (n < 2048) {
            src = qw + (size_t)n * KDIM;
            if (tid == 0) g_bias[n] = qb[n];
        } else if (n < 4096) {
            src = kw + (size_t)(n - 2048) * KDIM;
            if (tid == 0) g_bias[n] = kb[n - 2048];
        } else {
            src = vw + (size_t)(n - 4096) * KDIM;
            if (tid == 0) g_bias[n] = vb[n - 4096];
        }
        const float4* sr = reinterpret_cast<const float4*>(src);
        uint2* rowp = reinterpret_cast<uint2*>(g_W + (size_t)n * KDIM);
        #pragma unroll
        for (int jj = 0; jj < 2; jj++) {
            const int j = tid + 256 * jj;
            const float4 v = sr[j];
            rowp[j] = pack4h(v.x, v.y, v.z, v.w);
        }
        return;
    }

    // ---- LayerNorm path ----
    const int row = blockIdx.x;
    const float4* xr = reinterpret_cast<const float4*>(x + (size_t)row * KDIM);

    float4 v0 = xr[tid];
    float4 v1 = xr[tid + 256];

    float s = v0.x + v0.y + v0.z + v0.w + v1.x + v1.y + v1.z + v1.w;
    float q = v0.x*v0.x + v0.y*v0.y + v0.z*v0.z + v0.w*v0.w +
              v1.x*v1.x + v1.y*v1.y + v1.z*v1.z + v1.w*v1.w;

    #pragma unroll
    for (int o = 16; o > 0; o >>= 1) {
        s += __shfl_xor_sync(0xffffffffu, s, o);
        q += __shfl_xor_sync(0xffffffffu, q, o);
    }

    __shared__ float red[2][8];
    __shared__ float mu_s, rs_s;
    const int wid = tid >> 5, lane = tid & 31;
    if (lane == 0) { red[0][wid] = s; red[1][wid] = q; }
    __syncthreads();
    if (tid == 0) {
        float ss = 0.f, qq = 0.f;
        #pragma unroll
        for (int i = 0; i < 8; i++) { ss += red[0][i]; qq += red[1][i]; }
        float mu  = ss * (1.0f / KDIM);
        float var = qq * (1.0f / KDIM) - mu * mu;
        mu_s = mu;
        rs_s = rsqrtf(var + LN_EPS);
    }
    __syncthreads();
    const float mu = mu_s, rs = rs_s;

    const float4* wr = reinterpret_cast<const float4*>(nw);
    const float4* br = reinterpret_cast<const float4*>(nb);
    uint2* rowp = reinterpret_cast<uint2*>(g_A + (size_t)row * KDIM);

    #pragma unroll
    for (int jj = 0; jj < 2; jj++) {
        const int j = tid + 256 * jj;          // float4-chunk index 0..511
        const float4 xv = jj ? v1 : v0;
        const float4 wv = wr[j];
        const float4 bv = br[j];
        float o0 = (xv.x - mu) * rs * wv.x + bv.x;
        float o1 = (xv.y - mu) * rs * wv.y + bv.y;
        float o2 = (xv.z - mu) * rs * wv.z + bv.z;
        float o3 = (xv.w - mu) * rs * wv.w + bv.w;
        rowp[j] = pack4h(o0, o1, o2, o3);
    }
}

// ====================================================================
// Kernel 2: fp16 mma.sync GEMM, C[8192x6144] = A[8192x2048] * W[6144x2048]^T
//   256 threads: 8 warps = 2 (M) x 4 (N); warp tile 64x32; BK=64,
//   3 stages, 2 CTAs/SM.  Prefetch at front of iteration (R7-proven
//   placement); rotating stage pointers instead of kt%NSTAGE; B-fragment
//   ldmatrix issued before A so first-MMA operands complete earliest.
// ====================================================================
__global__ __launch_bounds__(256, 2)
void qkv_gemm_kernel(float* __restrict__ out)
{
    extern __shared__ char smem[];
    const int tid  = threadIdx.x;
    const int wid  = tid >> 5;
    const int lane = tid & 31;
    const int wm   = wid & 1;       // 0..1  (64 rows each)
    const int wn   = wid >> 1;      // 0..3  (32 cols each)
    const uint32_t sbase = smem_u32(smem);
    const uint32_t send  = sbase + NSTAGE * STAGE_BYTES;

    // tile mapping with group-of-8 m-tile swizzle for L2 reuse
    const int NT = NCOLS / BN;              // 48
    const int GM = 8;
    const int bid = blockIdx.x;
    const int grp = bid / (GM * NT);
    const int rem = bid % (GM * NT);
    const int mt_ = grp * GM + (rem % GM);
    const int nt_ = rem / GM;
    const int m0 = mt_ * BM;
    const int n0 = nt_ * BN;

    const __half* Ag = g_A + (size_t)m0 * KDIM;
    const __half* Wg = g_W + (size_t)n0 * KDIM;

    // per-thread cp.async dest offsets (4 rows x 16B each for A and B)
    const int cr = tid >> 3;                 // row   0..31 (base)
    const int cc = tid & 7;                  // 16B col 0..7
    const uint32_t coff[4] = {
        swz128((uint32_t)((cr +  0) * 128 + cc * 16)),
        swz128((uint32_t)((cr + 32) * 128 + cc * 16)),
        swz128((uint32_t)((cr + 64) * 128 + cc * 16)),
        swz128((uint32_t)((cr + 96) * 128 + cc * 16)),
    };

    auto load_stage = [&](uint32_t st, int kc) {
        const int k0 = kc * BK;
        #pragma unroll
        for (int j = 0; j < 4; j++)
            cp16(st + coff[j], Ag + (size_t)(cr + 32 * j) * KDIM + k0 + cc * 8);
        #pragma unroll
        for (int j = 0; j < 4; j++)
            cp16(st + A_TILE_BYTES + coff[j],
                 Wg + (size_t)(cr + 32 * j) * KDIM + k0 + cc * 8);
        cp_commit();
    };

    float acc[4][4][4];
    #pragma unroll
    for (int i = 0; i < 4; i++)
        #pragma unroll
        for (int j = 0; j < 4; j++)
            #pragma unroll
            for (int c = 0; c < 4; c++) acc[i][j][c] = 0.f;

    // prologue: 2 chunks in flight
    load_stage(sbase,               0);
    load_stage(sbase + STAGE_BYTES, 1);

    // precomputed lane pieces for ldmatrix addressing
    const int a_row_lane = lane & 15;                        // row within m16
    const int a_k_lane   = (lane >> 4) * 8;                  // k half
    const int b_row_lane = (lane & 7) + ((lane >> 4) << 3);  // row within n16
    const int b_k_lane   = ((lane >> 3) & 1) * 8;            // k half

    // rotating stage pointers: read stage and write stage (write = read+2 mod 3)
    uint32_t stRead  = sbase;
    uint32_t stWrite = sbase + 2 * STAGE_BYTES;

    #pragma unroll 1
    for (int kt = 0; kt < NKT; kt++) {
        // groups issued so far = kt + 2 (empty commits keep this invariant at
        // the tail); waiting for <=1 pending implies chunk kt is complete.
        asm volatile("cp.async.wait_group 1;" ::: "memory");
        __syncthreads();

        if (kt + 2 < NKT) load_stage(stWrite, kt + 2);
        else              cp_commit();   // empty group: keeps count aligned

        const uint32_t aBase = stRead;
        const uint32_t bBase = stRead + A_TILE_BYTES;

        #pragma unroll
        for (int ks = 0; ks < 4; ks++) {
            const int k0 = ks * 16;
            // B fragments first: first MMA consumes bf[0..] and af[0]
            uint32_t bf[4][2];
            #pragma unroll
            for (int p = 0; p < 2; p++) {
                const int rown = wn * 32 + p * 16 + b_row_lane;
                const uint32_t addr =
                    bBase + swz128((uint32_t)(rown * 128 + (k0 + b_k_lane) * 2));
                uint32_t r[4];
                ldsm_x4(addr, r);
                bf[2*p][0] = r[0]; bf[2*p][1] = r[1];
                bf[2*p+1][0] = r[2]; bf[2*p+1][1] = r[3];
            }
            uint32_t af[4][4];
            #pragma unroll
            for (int mt = 0; mt < 4; mt++) {
                const int row = wm * 64 + mt * 16 + a_row_lane;
                const uint32_t addr =
                    aBase + swz128((uint32_t)(row * 128 + (k0 + a_k_lane) * 2));
                ldsm_x4(addr, af[mt]);
            }
            #pragma unroll
            for (int mt = 0; mt < 4; mt++)
                #pragma unroll
                for (int nt = 0; nt < 4; nt++)
                    mma_f16(acc[mt][nt], af[mt], bf[nt][0], bf[nt][1]);
        }

        // rotate stage pointers (wrap at NSTAGE)
        stRead  += STAGE_BYTES;  if (stRead  == send) stRead  = sbase;
        stWrite += STAGE_BYTES;  if (stWrite == send) stWrite = sbase;
    }

    // epilogue: bias + direct stores (32B-sector aligned float2 per quad)
    const int gid = lane >> 2;       // 0..7 row within m8
    const int tq  = lane & 3;        // col pair
    float bb[4][2];
    #pragma unroll
    for (int nt = 0; nt < 4; nt++) {
        const int col = n0 + wn * 32 + nt * 8 + tq * 2;
        bb[nt][0] = g_bias[col];
        bb[nt][1] = g_bias[col + 1];
    }
    #pragma unroll
    for (int mt = 0; mt < 4; mt++) {
        const int row = m0 + wm * 64 + mt * 16 + gid;
        #pragma unroll
        for (int nt = 0; nt < 4; nt++) {
            const int col = n0 + wn * 32 + nt * 8 + tq * 2;
            float2 v0, v1;
            v0.x = acc[mt][nt][0] + bb[nt][0];
            v0.y = acc[mt][nt][1] + bb[nt][1];
            v1.x = acc[mt][nt][2] + bb[nt][0];
            v1.y = acc[mt][nt][3] + bb[nt][1];
            *reinterpret_cast<float2*>(out + (size_t)row * NCOLS + col) = v0;
            *reinterpret_cast<float2*>(out + (size_t)(row + 8) * NCOLS + col) = v1;
        }
    }
}

// ====================================================================
// launch
// ====================================================================
extern "C" void kernel_launch(void* const* d_in, const int* in_sizes, int n_in,
                              void* d_out, int out_size)
{
    const float* x  = (const float*)d_in[0];
    const float* nw = (const float*)d_in[1];
    const float* nb = (const float*)d_in[2];
    const float* qw = (const float*)d_in[3];
    const float* qb = (const float*)d_in[4];
    const float* kw = (const float*)d_in[5];
    const float* kb = (const float*)d_in[6];
    const float* vw = (const float*)d_in[7];
    const float* vb = (const float*)d_in[8];
    float* out = (float*)d_out;

    cudaFuncSetAttribute(qkv_gemm_kernel,
                         cudaFuncAttributeMaxDynamicSharedMemorySize, GEMM_SMEM);

    prep_kernel<<<MROWS + NCOLS, 256>>>(x, nw, nb, qw, kw, vw, qb, kb, vb);
    qkv_gemm_kernel<<<(MROWS / BM) * (NCOLS / BN), 256, GEMM_SMEM>>>(out);
}